// round 11
// baseline (speedup 1.0000x reference)
#include <cuda_runtime.h>
#include <cstdint>

// out[n,h,d] = sum_j x[n,j,d] * FM[j+1,h] * Agg[0,j,h]
// (the reference's sort/gap/code machinery telescopes to this linear map)
//
// R10: terminal trim. Chip-level ~700 GB/s burst ceiling (8 structurally
// different kernels, one band) => only the non-memory head remains. Issue
// the x loads FIRST, build W in registers (no smem, no __syncthreads),
// so the DRAM stream starts at cycle ~0.

#define S_DIM 16
#define H_DIM 4
#define N_DIM 128
#define D_DIM 512

__global__ void __launch_bounds__(256) cie_linear_kernel(
    const float* __restrict__ x,     // (N, S, D)
    const float* __restrict__ FM,    // (S+1, H)
    const float* __restrict__ Agg,   // (1, S, H)
    float* __restrict__ out)         // (N, H, D)
{
    const int tid   = threadIdx.x;
    const int n     = blockIdx.x >> 1;
    const int dhalf = blockIdx.x & 1;
    const int col   = tid >> 2;        // 0..63 local d4 column
    const int jg    = tid & 3;         // j-group: j = jg*4 .. jg*4+3
    const int d4    = dhalf * 64 + col;

    const float4* xp = reinterpret_cast<const float4*>(
        x + (size_t)n * S_DIM * D_DIM) + d4;

    // Long-pole DRAM loads first — nothing in front of them.
    float4 v0 = __ldg(xp + (jg * 4 + 0) * (D_DIM / 4));
    float4 v1 = __ldg(xp + (jg * 4 + 1) * (D_DIM / 4));
    float4 v2 = __ldg(xp + (jg * 4 + 2) * (D_DIM / 4));
    float4 v3 = __ldg(xp + (jg * 4 + 3) * (D_DIM / 4));

    // W in registers; uniform per-jg addresses ride under x-load latency.
    float W0[H_DIM], W1[H_DIM], W2[H_DIM], W3[H_DIM];
#pragma unroll
    for (int h = 0; h < H_DIM; h++) {
        const int j0 = jg * 4;
        W0[h] = __ldg(FM + (j0 + 1) * H_DIM + h) * __ldg(Agg + (j0 + 0) * H_DIM + h);
        W1[h] = __ldg(FM + (j0 + 2) * H_DIM + h) * __ldg(Agg + (j0 + 1) * H_DIM + h);
        W2[h] = __ldg(FM + (j0 + 3) * H_DIM + h) * __ldg(Agg + (j0 + 2) * H_DIM + h);
        W3[h] = __ldg(FM + (j0 + 4) * H_DIM + h) * __ldg(Agg + (j0 + 3) * H_DIM + h);
    }

    float4 acc[H_DIM];
#pragma unroll
    for (int h = 0; h < H_DIM; h++) {
        float ax, ay, az, aw;
        ax = v0.x * W0[h]; ay = v0.y * W0[h];
        az = v0.z * W0[h]; aw = v0.w * W0[h];
        ax = fmaf(v1.x, W1[h], ax); ay = fmaf(v1.y, W1[h], ay);
        az = fmaf(v1.z, W1[h], az); aw = fmaf(v1.w, W1[h], aw);
        ax = fmaf(v2.x, W2[h], ax); ay = fmaf(v2.y, W2[h], ay);
        az = fmaf(v2.z, W2[h], az); aw = fmaf(v2.w, W2[h], aw);
        ax = fmaf(v3.x, W3[h], ax); ay = fmaf(v3.y, W3[h], ay);
        az = fmaf(v3.z, W3[h], az); aw = fmaf(v3.w, W3[h], aw);
        acc[h] = make_float4(ax, ay, az, aw);
    }

    // Fold the 4 j-groups across adjacent lanes (xor 1, then 2).
#pragma unroll
    for (int m = 1; m <= 2; m <<= 1) {
#pragma unroll
        for (int h = 0; h < H_DIM; h++) {
            acc[h].x += __shfl_xor_sync(0xffffffffu, acc[h].x, m);
            acc[h].y += __shfl_xor_sync(0xffffffffu, acc[h].y, m);
            acc[h].z += __shfl_xor_sync(0xffffffffu, acc[h].z, m);
            acc[h].w += __shfl_xor_sync(0xffffffffu, acc[h].w, m);
        }
    }

    // All 4 lanes of a d4 group now hold full sums; lane jg stores h=jg.
    float4* op = reinterpret_cast<float4*>(
        out + (size_t)n * H_DIM * D_DIM) + d4;
    op[jg * (D_DIM / 4)] = acc[jg];
}

extern "C" void kernel_launch(void* const* d_in, const int* in_sizes, int n_in,
                              void* d_out, int out_size) {
    const float* x   = (const float*)d_in[0];   // (128,16,512) f32
    const float* FM  = (const float*)d_in[1];   // (17,4) f32
    const float* Agg = (const float*)d_in[2];   // (1,16,4) f32
    // d_in[3] = source_index, unused: the table gather telescopes away.
    float* out = (float*)d_out;                 // (128,4,512) f32

    cie_linear_kernel<<<N_DIM * 2, 256>>>(x, FM, Agg, out);
}